// round 2
// baseline (speedup 1.0000x reference)
#include <cuda_runtime.h>
#include <math.h>

#define D_DIM   1024
#define I_DIM   4096
#define E_NUM   8
#define TOPK    2
#define T_MAX   2048
#define NPOS    4608          // 2*T_MAX + E_NUM*64 (per-expert padding to 64)
#define NROWTILE (NPOS/64)    // 72

#define BM 64
#define BN 64
#define BK 16

// ---------------- scratch (static device allocations; no cudaMalloc) --------
__device__ int   g_counts[E_NUM];
__device__ int   g_offsets[E_NUM + 1];
__device__ int   g_cursor[E_NUM];
__device__ int   g_tile_expert[NROWTILE];
__device__ int   g_pos_token[NPOS];
__device__ float g_pos_wt[NPOS];
__device__ int   g_slot_pos[T_MAX * TOPK];
__device__ int   g_tok_eidx[T_MAX * TOPK];
__device__ float g_tok_ewt[T_MAX * TOPK];
__device__ float g_h[(size_t)NPOS * I_DIM];   // ~75.5 MB
__device__ float g_y[(size_t)NPOS * D_DIM];   // ~18.9 MB

// ---------------- init -------------------------------------------------------
__global__ void init_kernel() {
    int i = blockIdx.x * blockDim.x + threadIdx.x;
    if (i < E_NUM) g_counts[i] = 0;
    if (i < NPOS) { g_pos_token[i] = -1; g_pos_wt[i] = 0.f; }
}

// ---------------- gating: one warp per token --------------------------------
__global__ void gate_kernel(const float* __restrict__ x,
                            const float* __restrict__ gw, int T) {
    int gtid = blockIdx.x * blockDim.x + threadIdx.x;
    int warp = gtid >> 5;
    int lane = gtid & 31;
    if (warp >= T) return;
    const float* xr = x + (size_t)warp * D_DIM;

    float acc[E_NUM];
#pragma unroll
    for (int e = 0; e < E_NUM; e++) acc[e] = 0.f;

    for (int k = lane; k < D_DIM; k += 32) {
        float xv = xr[k];
#pragma unroll
        for (int e = 0; e < E_NUM; e++)
            acc[e] = fmaf(xv, gw[e * D_DIM + k], acc[e]);
    }
#pragma unroll
    for (int e = 0; e < E_NUM; e++) {
#pragma unroll
        for (int off = 16; off > 0; off >>= 1)
            acc[e] += __shfl_down_sync(0xFFFFFFFFu, acc[e], off);
    }
    if (lane == 0) {
        // top-1 (strict >, keeps lowest index on ties like lax.top_k)
        int i0 = 0;
#pragma unroll
        for (int e = 1; e < E_NUM; e++) if (acc[e] > acc[i0]) i0 = e;
        int i1 = (i0 == 0) ? 1 : 0;
#pragma unroll
        for (int e = 0; e < E_NUM; e++)
            if (e != i0 && acc[e] > acc[i1]) i1 = e;
        // softmax ratio: Z cancels in renormalization
        float m = fmaxf(acc[i0], acc[i1]);
        float p0 = __expf(acc[i0] - m);
        float p1 = __expf(acc[i1] - m);
        float s = p0 + p1;
        int base = warp * TOPK;
        g_tok_eidx[base + 0] = i0; g_tok_ewt[base + 0] = p0 / s;
        g_tok_eidx[base + 1] = i1; g_tok_ewt[base + 1] = p1 / s;
        atomicAdd(&g_counts[i0], 1);
        atomicAdd(&g_counts[i1], 1);
    }
}

// ---------------- offsets + tile->expert table (tiny) ------------------------
__global__ void offsets_kernel() {
    if (threadIdx.x == 0 && blockIdx.x == 0) {
        int total = 0;
        for (int e = 0; e < E_NUM; e++) {
            g_offsets[e] = total;
            g_cursor[e]  = total;
            total += (g_counts[e] + 63) & ~63;   // pad group to 64 rows
        }
        g_offsets[E_NUM] = total;
        for (int t = 0; t < NROWTILE; t++) {
            int r0 = t * BM;
            int e = 0;
            while (e < E_NUM - 1 && r0 >= g_offsets[e + 1]) e++;
            g_tile_expert[t] = (r0 < total) ? e : -1;
        }
    }
}

// ---------------- scatter ----------------------------------------------------
__global__ void scatter_kernel(int T) {
    int idx = blockIdx.x * blockDim.x + threadIdx.x;
    if (idx >= T * TOPK) return;
    int e = g_tok_eidx[idx];
    int pos = atomicAdd(&g_cursor[e], 1);
    g_pos_token[pos] = idx >> 1;
    g_pos_wt[pos]    = g_tok_ewt[idx];
    g_slot_pos[idx]  = pos;
}

// ---------------- GEMM1: h = silu(X w1^T) * (X w3^T), per expert group -------
__global__ __launch_bounds__(256)
void gemm1_kernel(const float* __restrict__ x,
                  const float* __restrict__ w1,
                  const float* __restrict__ w3) {
    __shared__ __align__(16) float As [BK][BM + 4];
    __shared__ __align__(16) float B1s[BK][BN + 4];
    __shared__ __align__(16) float B3s[BK][BN + 4];
    __shared__ int s_tok[BM];

    int e = g_tile_expert[blockIdx.y];
    if (e < 0) return;
    int r0 = blockIdx.y * BM;

    int c0  = blockIdx.x * BN;
    int tid = threadIdx.x;
    if (tid < BM) s_tok[tid] = g_pos_token[r0 + tid];
    __syncthreads();

    int lr = tid >> 2;          // 0..63
    int lk = (tid & 3) * 4;     // 0,4,8,12
    const float* w1p = w1 + ((size_t)e * I_DIM + c0 + lr) * D_DIM + lk;
    const float* w3p = w3 + ((size_t)e * I_DIM + c0 + lr) * D_DIM + lk;
    int tok = s_tok[lr];
    const float* xp = (tok >= 0) ? (x + (size_t)tok * D_DIM + lk) : nullptr;

    float acc1[4][4], acc3[4][4];
#pragma unroll
    for (int i = 0; i < 4; i++)
#pragma unroll
        for (int j = 0; j < 4; j++) { acc1[i][j] = 0.f; acc3[i][j] = 0.f; }

    int tx = tid & 15, ty = tid >> 4;

    for (int k0 = 0; k0 < D_DIM; k0 += BK) {
        float4 a  = xp ? *(const float4*)(xp + k0) : make_float4(0.f, 0.f, 0.f, 0.f);
        float4 b1 = *(const float4*)(w1p + k0);
        float4 b3 = *(const float4*)(w3p + k0);
        As [lk + 0][lr] = a.x;  As [lk + 1][lr] = a.y;
        As [lk + 2][lr] = a.z;  As [lk + 3][lr] = a.w;
        B1s[lk + 0][lr] = b1.x; B1s[lk + 1][lr] = b1.y;
        B1s[lk + 2][lr] = b1.z; B1s[lk + 3][lr] = b1.w;
        B3s[lk + 0][lr] = b3.x; B3s[lk + 1][lr] = b3.y;
        B3s[lk + 2][lr] = b3.z; B3s[lk + 3][lr] = b3.w;
        __syncthreads();
#pragma unroll
        for (int kk = 0; kk < BK; kk++) {
            float4 av  = *(const float4*)&As [kk][ty * 4];
            float4 b1v = *(const float4*)&B1s[kk][tx * 4];
            float4 b3v = *(const float4*)&B3s[kk][tx * 4];
            float am[4] = {av.x, av.y, av.z, av.w};
            float bm1[4] = {b1v.x, b1v.y, b1v.z, b1v.w};
            float bm3[4] = {b3v.x, b3v.y, b3v.z, b3v.w};
#pragma unroll
            for (int i = 0; i < 4; i++)
#pragma unroll
                for (int j = 0; j < 4; j++) {
                    acc1[i][j] = fmaf(am[i], bm1[j], acc1[i][j]);
                    acc3[i][j] = fmaf(am[i], bm3[j], acc3[i][j]);
                }
        }
        __syncthreads();
    }

    // epilogue: h = silu(a1) * a3
    int colbase = c0 + tx * 4;
#pragma unroll
    for (int i = 0; i < 4; i++) {
        int row = r0 + ty * 4 + i;
        float* hp = g_h + (size_t)row * I_DIM + colbase;
        float4 hv;
        float a;
        a = acc1[i][0]; hv.x = a * (1.f / (1.f + __expf(-a))) * acc3[i][0];
        a = acc1[i][1]; hv.y = a * (1.f / (1.f + __expf(-a))) * acc3[i][1];
        a = acc1[i][2]; hv.z = a * (1.f / (1.f + __expf(-a))) * acc3[i][2];
        a = acc1[i][3]; hv.w = a * (1.f / (1.f + __expf(-a))) * acc3[i][3];
        *(float4*)hp = hv;
    }
}

// ---------------- GEMM2: y = (h @ w2^T) * routing_weight ---------------------
__global__ __launch_bounds__(256)
void gemm2_kernel(const float* __restrict__ w2) {
    __shared__ __align__(16) float As[BK][BM + 4];
    __shared__ __align__(16) float Bs[BK][BN + 4];
    __shared__ float s_wt[BM];

    int e = g_tile_expert[blockIdx.y];
    if (e < 0) return;
    int r0 = blockIdx.y * BM;

    int c0  = blockIdx.x * BN;
    int tid = threadIdx.x;
    if (tid < BM) s_wt[tid] = g_pos_wt[r0 + tid];
    __syncthreads();

    int lr = tid >> 2;
    int lk = (tid & 3) * 4;
    const float* ap = g_h + (size_t)(r0 + lr) * I_DIM + lk;
    const float* bp = w2 + ((size_t)e * D_DIM + c0 + lr) * I_DIM + lk;

    float acc[4][4];
#pragma unroll
    for (int i = 0; i < 4; i++)
#pragma unroll
        for (int j = 0; j < 4; j++) acc[i][j] = 0.f;

    int tx = tid & 15, ty = tid >> 4;

    for (int k0 = 0; k0 < I_DIM; k0 += BK) {
        float4 a = *(const float4*)(ap + k0);
        float4 b = *(const float4*)(bp + k0);
        As[lk + 0][lr] = a.x; As[lk + 1][lr] = a.y;
        As[lk + 2][lr] = a.z; As[lk + 3][lr] = a.w;
        Bs[lk + 0][lr] = b.x; Bs[lk + 1][lr] = b.y;
        Bs[lk + 2][lr] = b.z; Bs[lk + 3][lr] = b.w;
        __syncthreads();
#pragma unroll
        for (int kk = 0; kk < BK; kk++) {
            float4 av = *(const float4*)&As[kk][ty * 4];
            float4 bv = *(const float4*)&Bs[kk][tx * 4];
            float am[4] = {av.x, av.y, av.z, av.w};
            float bm[4] = {bv.x, bv.y, bv.z, bv.w};
#pragma unroll
            for (int i = 0; i < 4; i++)
#pragma unroll
                for (int j = 0; j < 4; j++)
                    acc[i][j] = fmaf(am[i], bm[j], acc[i][j]);
        }
        __syncthreads();
    }

    int colbase = c0 + tx * 4;
#pragma unroll
    for (int i = 0; i < 4; i++) {
        int row = r0 + ty * 4 + i;
        float wt = s_wt[ty * 4 + i];
        float* yp = g_y + (size_t)row * D_DIM + colbase;
        float4 yv;
        yv.x = acc[i][0] * wt; yv.y = acc[i][1] * wt;
        yv.z = acc[i][2] * wt; yv.w = acc[i][3] * wt;
        *(float4*)yp = yv;
    }
}

// ---------------- combine: out[t] = y[p0] + y[p1] ----------------------------
__global__ void combine_kernel(float* __restrict__ out, int T) {
    int idx = blockIdx.x * blockDim.x + threadIdx.x;   // over T*D/4 float4s
    int total = T * (D_DIM / 4);
    if (idx >= total) return;
    int t = idx / (D_DIM / 4);
    int d4 = idx - t * (D_DIM / 4);
    int p0 = g_slot_pos[2 * t];
    int p1 = g_slot_pos[2 * t + 1];
    const float4* y0 = (const float4*)(g_y + (size_t)p0 * D_DIM) + d4;
    const float4* y1 = (const float4*)(g_y + (size_t)p1 * D_DIM) + d4;
    float4 a = *y0, b = *y1;
    float4 r;
    r.x = a.x + b.x; r.y = a.y + b.y; r.z = a.z + b.z; r.w = a.w + b.w;
    ((float4*)out)[idx] = r;
}

// ---------------- launch -----------------------------------------------------
extern "C" void kernel_launch(void* const* d_in, const int* in_sizes, int n_in,
                              void* d_out, int out_size) {
    const float* x  = (const float*)d_in[0];
    const float* gw = (const float*)d_in[1];
    const float* w1 = (const float*)d_in[2];
    const float* w2 = (const float*)d_in[3];
    const float* w3 = (const float*)d_in[4];
    float* out = (float*)d_out;

    int T = in_sizes[0] / D_DIM;   // 2048
    if (T > T_MAX) T = T_MAX;

    init_kernel<<<(NPOS + 255) / 256, 256>>>();
    gate_kernel<<<(T * 32 + 255) / 256, 256>>>(x, gw, T);
    offsets_kernel<<<1, 32>>>();
    scatter_kernel<<<(T * TOPK + 255) / 256, 256>>>(T);

    dim3 grid1(I_DIM / BN, NROWTILE);
    gemm1_kernel<<<grid1, 256>>>(x, w1, w3);

    dim3 grid2(D_DIM / BN, NROWTILE);
    gemm2_kernel<<<grid2, 256>>>(w2);

    combine_kernel<<<(T * (D_DIM / 4) + 255) / 256, 256>>>(out, T);
}

// round 7
// speedup vs baseline: 2.1804x; 2.1804x over previous
#include <cuda_runtime.h>
#include <cuda_bf16.h>
#include <cstdint>
#include <math.h>

#define D_DIM 1024
#define I_DIM 4096
#define E_NUM 8
#define TOPK  2
#define T_MAX 2048
#define PADR  128
#define NPOS  (T_MAX*TOPK + E_NUM*PADR)   // 5120
#define NROWTILE (NPOS/PADR)              // 40

// ---- smem layouts (pitch 80B per 32-bf16 row; ldmatrix conflict-free) ------
#define STAGE1 40960
#define O1_AH  0
#define O1_AL  10240
#define O1_B1H 20480
#define O1_B1L 25600
#define O1_B3H 30720
#define O1_B3L 35840
#define SMEM1  (512 + 2*STAGE1)           // 82432

#define STAGE2 30720
#define O2_AH  0
#define O2_AL  10240
#define O2_BH  20480
#define O2_BL  25600
#define SMEM2  (512 + 2*STAGE2)           // 61952

// ---------------- scratch ----------------------------------------------------
__device__ int   g_counts[E_NUM];
__device__ int   g_offsets[E_NUM + 1];
__device__ int   g_cursor[E_NUM];
__device__ int   g_tile_expert[NROWTILE];
__device__ int   g_pos_token[NPOS];
__device__ float g_pos_wt[NPOS];
__device__ int   g_slot_pos[T_MAX * TOPK];
__device__ int   g_tok_eidx[T_MAX * TOPK];
__device__ float g_tok_ewt[T_MAX * TOPK];
__device__ float g_h[(size_t)NPOS * I_DIM];   // ~84 MB
__device__ float g_y[(size_t)NPOS * D_DIM];   // ~21 MB

// ---------------- helpers ----------------------------------------------------
__device__ __forceinline__ uint32_t smem_u32(const void* p) {
    uint32_t a;
    asm("{ .reg .u64 t; cvta.to.shared.u64 t, %1; cvt.u32.u64 %0, t; }" : "=r"(a) : "l"(p));
    return a;
}
__device__ __forceinline__ void ldm_x4(uint32_t* r, uint32_t addr) {
    asm volatile("ldmatrix.sync.aligned.m8n8.x4.shared.b16 {%0,%1,%2,%3}, [%4];"
        : "=r"(r[0]), "=r"(r[1]), "=r"(r[2]), "=r"(r[3]) : "r"(addr));
}
__device__ __forceinline__ void mma_bf16(float* c, const uint32_t* a, uint32_t b0, uint32_t b1) {
    asm volatile("mma.sync.aligned.m16n8k16.row.col.f32.bf16.bf16.f32 "
        "{%0,%1,%2,%3}, {%4,%5,%6,%7}, {%8,%9}, {%0,%1,%2,%3};"
        : "+f"(c[0]), "+f"(c[1]), "+f"(c[2]), "+f"(c[3])
        : "r"(a[0]), "r"(a[1]), "r"(a[2]), "r"(a[3]), "r"(b0), "r"(b1));
}
// fp32x4 -> bf16 hi/lo, store 8B each
__device__ __forceinline__ void cvt_store(char* dh, char* dl, float4 v) {
    __nv_bfloat162 h0 = __floats2bfloat162_rn(v.x, v.y);
    __nv_bfloat162 h1 = __floats2bfloat162_rn(v.z, v.w);
    __nv_bfloat162 l0 = __floats2bfloat162_rn(v.x - __bfloat162float(h0.x),
                                              v.y - __bfloat162float(h0.y));
    __nv_bfloat162 l1 = __floats2bfloat162_rn(v.z - __bfloat162float(h1.x),
                                              v.w - __bfloat162float(h1.y));
    *(uint2*)dh = make_uint2(reinterpret_cast<uint32_t&>(h0), reinterpret_cast<uint32_t&>(h1));
    *(uint2*)dl = make_uint2(reinterpret_cast<uint32_t&>(l0), reinterpret_cast<uint32_t&>(l1));
}

// ---------------- small kernels ----------------------------------------------
__global__ void init_kernel() {
    int i = blockIdx.x * blockDim.x + threadIdx.x;
    if (i < E_NUM) g_counts[i] = 0;
    if (i < NPOS) { g_pos_token[i] = -1; g_pos_wt[i] = 0.f; }
}

__global__ void gate_kernel(const float* __restrict__ x,
                            const float* __restrict__ gw, int T) {
    int gtid = blockIdx.x * blockDim.x + threadIdx.x;
    int warp = gtid >> 5, lane = gtid & 31;
    if (warp >= T) return;
    const float* xr = x + (size_t)warp * D_DIM;
    float acc[E_NUM];
#pragma unroll
    for (int e = 0; e < E_NUM; e++) acc[e] = 0.f;
    for (int k = lane; k < D_DIM; k += 32) {
        float xv = xr[k];
#pragma unroll
        for (int e = 0; e < E_NUM; e++)
            acc[e] = fmaf(xv, gw[e * D_DIM + k], acc[e]);
    }
#pragma unroll
    for (int e = 0; e < E_NUM; e++)
#pragma unroll
        for (int off = 16; off > 0; off >>= 1)
            acc[e] += __shfl_down_sync(0xFFFFFFFFu, acc[e], off);
    if (lane == 0) {
        int i0 = 0;
#pragma unroll
        for (int e = 1; e < E_NUM; e++) if (acc[e] > acc[i0]) i0 = e;
        int i1 = (i0 == 0) ? 1 : 0;
#pragma unroll
        for (int e = 0; e < E_NUM; e++)
            if (e != i0 && acc[e] > acc[i1]) i1 = e;
        float m = fmaxf(acc[i0], acc[i1]);
        float p0 = __expf(acc[i0] - m), p1 = __expf(acc[i1] - m);
        float s = p0 + p1;
        int base = warp * TOPK;
        g_tok_eidx[base + 0] = i0; g_tok_ewt[base + 0] = p0 / s;
        g_tok_eidx[base + 1] = i1; g_tok_ewt[base + 1] = p1 / s;
        atomicAdd(&g_counts[i0], 1);
        atomicAdd(&g_counts[i1], 1);
    }
}

__global__ void offsets_kernel() {
    if (threadIdx.x == 0 && blockIdx.x == 0) {
        int total = 0;
        for (int e = 0; e < E_NUM; e++) {
            g_offsets[e] = total;
            g_cursor[e]  = total;
            total += (g_counts[e] + PADR - 1) & ~(PADR - 1);
        }
        g_offsets[E_NUM] = total;
        for (int t = 0; t < NROWTILE; t++) {
            int r0 = t * PADR;
            int e = 0;
            while (e < E_NUM - 1 && r0 >= g_offsets[e + 1]) e++;
            g_tile_expert[t] = (r0 < total) ? e : -1;
        }
    }
}

__global__ void scatter_kernel(int T) {
    int idx = blockIdx.x * blockDim.x + threadIdx.x;
    if (idx >= T * TOPK) return;
    int e = g_tok_eidx[idx];
    int pos = atomicAdd(&g_cursor[e], 1);
    g_pos_token[pos] = idx >> 1;
    g_pos_wt[pos]    = g_tok_ewt[idx];
    g_slot_pos[idx]  = pos;
}

// ---------------- GEMM1: 128x64 tile; warps 0-7: D1, warps 8-15: D3 ----------
__global__ __launch_bounds__(512, 1)
void gemm1_kernel(const float* __restrict__ x,
                  const float* __restrict__ w1,
                  const float* __restrict__ w3) {
    extern __shared__ char sm[];
    int e = g_tile_expert[blockIdx.y];
    if (e < 0) return;
    int tid = threadIdx.x, lane = tid & 31, wid = tid >> 5;
    int r0 = blockIdx.y * PADR, c0 = blockIdx.x * 64;
    int* s_tok = (int*)sm;
    char* tiles = sm + 512;
    uint32_t tiles_u = smem_u32(sm) + 512;

    if (tid < 128) s_tok[tid] = g_pos_token[r0 + tid];
    __syncthreads();

    int wg = wid >> 3;            // 0: D1(w1), 1: D3(w3)
    int wl = wid & 7;
    int mrow = (wl >> 1) * 32;    // 0..96
    int ncol = (wl & 1) * 32;     // 0,32

    float c[2][4][4];
#pragma unroll
    for (int a = 0; a < 2; a++)
#pragma unroll
        for (int b = 0; b < 4; b++)
#pragma unroll
            for (int q = 0; q < 4; q++) c[a][b][q] = 0.f;

    float4 v[4];
    // load stage kc into regs v[]
    auto load_stage = [&](int kc) {
        int k0 = kc * 32;
#pragma unroll
        for (int it = 0; it < 4; it++) {
            int gid = it * 512 + tid;
            const float* src;
            if (gid < 1024) {
                int r = gid >> 3, c4 = gid & 7;
                int tok = s_tok[r];
                src = (tok >= 0) ? x + (size_t)tok * D_DIM + k0 + c4 * 4 : nullptr;
            } else if (gid < 1536) {
                int g = gid - 1024, r = g >> 3, c4 = g & 7;
                src = w1 + ((size_t)e * I_DIM + c0 + r) * D_DIM + k0 + c4 * 4;
            } else {
                int g = gid - 1536, r = g >> 3, c4 = g & 7;
                src = w3 + ((size_t)e * I_DIM + c0 + r) * D_DIM + k0 + c4 * 4;
            }
            v[it] = src ? *(const float4*)src : make_float4(0.f, 0.f, 0.f, 0.f);
        }
    };
    auto store_stage = [&](int st) {
        char* base = tiles + st * STAGE1;
#pragma unroll
        for (int it = 0; it < 4; it++) {
            int gid = it * 512 + tid;
            int oh, ol, r, c4;
            if (gid < 1024)      { r = gid >> 3;           c4 = gid & 7; oh = O1_AH;  ol = O1_AL;  }
            else if (gid < 1536) { int g = gid - 1024; r = g >> 3; c4 = g & 7; oh = O1_B1H; ol = O1_B1L; }
            else                 { int g = gid - 1536; r = g >> 3; c4 = g & 7; oh = O1_B3H; ol = O1_B3L; }
            int off = r * 80 + c4 * 8;
            cvt_store(base + oh + off, base + ol + off, v[it]);
        }
    };
    auto compute = [&](int st) {
        uint32_t su = tiles_u + st * STAGE1;
#pragma unroll
        for (int kk = 0; kk < 2; kk++) {
            int ko = kk * 32;  // 16 bf16 = 32B
            uint32_t ah[2][4], al[2][4];
#pragma unroll
            for (int mt = 0; mt < 2; mt++) {
                uint32_t aaddr = su + O1_AH
                    + (uint32_t)((mrow + mt * 16 + (lane & 15)) * 80 + ko + (lane >> 4) * 16);
                ldm_x4(ah[mt], aaddr);
                ldm_x4(al[mt], aaddr + (O1_AL - O1_AH));
            }
            uint32_t bbase = su + (wg ? O1_B3H : O1_B1H);
#pragma unroll
            for (int nt2 = 0; nt2 < 2; nt2++) {
                uint32_t bh[4], bl[4];
                uint32_t baddr = bbase
                    + (uint32_t)((ncol + nt2 * 16 + (lane & 15)) * 80 + ko + (lane >> 4) * 16);
                ldm_x4(bh, baddr);
                ldm_x4(bl, baddr + 5120);
#pragma unroll
                for (int mt = 0; mt < 2; mt++)
#pragma unroll
                    for (int sub = 0; sub < 2; sub++) {
                        float* cc = c[mt][nt2 * 2 + sub];
                        mma_bf16(cc, ah[mt], bh[sub], bh[sub + 2]);
                        mma_bf16(cc, al[mt], bh[sub], bh[sub + 2]);
                        mma_bf16(cc, ah[mt], bl[sub], bl[sub + 2]);
                    }
            }
        }
    };

    load_stage(0);
    store_stage(0);
    __syncthreads();
#pragma unroll 1
    for (int kc = 0; kc < 32; kc++) {
        int cur = kc & 1;
        if (kc < 31) load_stage(kc + 1);
        compute(cur);
        __syncthreads();
        if (kc < 31) { store_stage(cur ^ 1); __syncthreads(); }
    }

    // epilogue: D3 warps -> smem; D1 warps: h = silu(d1)*d3 -> g_h (fp32)
    float* stg = (float*)(sm + 512);   // [128][68]
    if (wg == 1) {
#pragma unroll
        for (int mt = 0; mt < 2; mt++)
#pragma unroll
            for (int nt = 0; nt < 4; nt++) {
                int row = mrow + mt * 16 + (lane >> 2);
                int col = ncol + nt * 8 + 2 * (lane & 3);
                float* cc = c[mt][nt];
                *(float2*)&stg[row * 68 + col]       = make_float2(cc[0], cc[1]);
                *(float2*)&stg[(row + 8) * 68 + col] = make_float2(cc[2], cc[3]);
            }
    }
    __syncthreads();
    if (wg == 0) {
#pragma unroll
        for (int mt = 0; mt < 2; mt++)
#pragma unroll
            for (int nt = 0; nt < 4; nt++) {
                int row = mrow + mt * 16 + (lane >> 2);
                int col = ncol + nt * 8 + 2 * (lane & 3);
                float* cc = c[mt][nt];
                float2 d3a = *(float2*)&stg[row * 68 + col];
                float2 d3b = *(float2*)&stg[(row + 8) * 68 + col];
                float h0 = cc[0] * d3a.x / (1.f + __expf(-cc[0]));
                float h1 = cc[1] * d3a.y / (1.f + __expf(-cc[1]));
                float h2 = cc[2] * d3b.x / (1.f + __expf(-cc[2]));
                float h3 = cc[3] * d3b.y / (1.f + __expf(-cc[3]));
                *(float2*)(g_h + (size_t)(r0 + row) * I_DIM + c0 + col)     = make_float2(h0, h1);
                *(float2*)(g_h + (size_t)(r0 + row + 8) * I_DIM + c0 + col) = make_float2(h2, h3);
            }
    }
}

// ---------------- GEMM2: 128x64 tile; warp m32n16; y = (h·w2ᵀ)*wt ------------
__global__ __launch_bounds__(512, 1)
void gemm2_kernel(const float* __restrict__ w2) {
    extern __shared__ char sm[];
    int e = g_tile_expert[blockIdx.y];
    if (e < 0) return;
    int tid = threadIdx.x, lane = tid & 31, wid = tid >> 5;
    int r0 = blockIdx.y * PADR, c0 = blockIdx.x * 64;
    char* tiles = sm + 512;
    uint32_t tiles_u = smem_u32(sm) + 512;

    int mrow = (wid >> 2) * 32;   // 0..96
    int ncol = (wid & 3) * 16;    // 0..48

    float c[2][2][4];
#pragma unroll
    for (int a = 0; a < 2; a++)
#pragma unroll
        for (int b = 0; b < 2; b++)
#pragma unroll
            for (int q = 0; q < 4; q++) c[a][b][q] = 0.f;

    float4 v[3];
    auto load_stage = [&](int kc) {
        int k0 = kc * 32;
#pragma unroll
        for (int it = 0; it < 3; it++) {
            int gid = it * 512 + tid;
            const float* src;
            if (gid < 1024) {
                int r = gid >> 3, c4 = gid & 7;
                src = g_h + (size_t)(r0 + r) * I_DIM + k0 + c4 * 4;
            } else {
                int g = gid - 1024, r = g >> 3, c4 = g & 7;
                src = w2 + ((size_t)e * D_DIM + c0 + r) * I_DIM + k0 + c4 * 4;
            }
            v[it] = *(const float4*)src;
        }
    };
    auto store_stage = [&](int st) {
        char* base = tiles + st * STAGE2;
#pragma unroll
        for (int it = 0; it < 3; it++) {
            int gid = it * 512 + tid;
            int oh, ol, r, c4;
            if (gid < 1024) { r = gid >> 3; c4 = gid & 7; oh = O2_AH; ol = O2_AL; }
            else            { int g = gid - 1024; r = g >> 3; c4 = g & 7; oh = O2_BH; ol = O2_BL; }
            int off = r * 80 + c4 * 8;
            cvt_store(base + oh + off, base + ol + off, v[it]);
        }
    };
    auto compute = [&](int st) {
        uint32_t su = tiles_u + st * STAGE2;
#pragma unroll
        for (int kk = 0; kk < 2; kk++) {
            int ko = kk * 32;
            uint32_t ah[2][4], al[2][4];
#pragma unroll
            for (int mt = 0; mt < 2; mt++) {
                uint32_t aaddr = su + O2_AH
                    + (uint32_t)((mrow + mt * 16 + (lane & 15)) * 80 + ko + (lane >> 4) * 16);
                ldm_x4(ah[mt], aaddr);
                ldm_x4(al[mt], aaddr + (O2_AL - O2_AH));
            }
            uint32_t bh[4], bl[4];
            uint32_t baddr = su + O2_BH
                + (uint32_t)((ncol + (lane & 15)) * 80 + ko + (lane >> 4) * 16);
            ldm_x4(bh, baddr);
            ldm_x4(bl, baddr + (O2_BL - O2_BH));
#pragma unroll
            for (int mt = 0; mt < 2; mt++)
#pragma unroll
                for (int sub = 0; sub < 2; sub++) {
                    float* cc = c[mt][sub];
                    mma_bf16(cc, ah[mt], bh[sub], bh[sub + 2]);
                    mma_bf16(cc, al[mt], bh[sub], bh[sub + 2]);
                    mma_bf16(cc, ah[mt], bl[sub], bl[sub + 2]);
                }
        }
    };

    load_stage(0);
    store_stage(0);
    __syncthreads();
#pragma unroll 1
    for (int kc = 0; kc < 128; kc++) {
        int cur = kc & 1;
        if (kc < 127) load_stage(kc + 1);
        compute(cur);
        __syncthreads();
        if (kc < 127) { store_stage(cur ^ 1); __syncthreads(); }
    }

#pragma unroll
    for (int mt = 0; mt < 2; mt++) {
        int row = mrow + mt * 16 + (lane >> 2);
        float wa = g_pos_wt[r0 + row];
        float wb = g_pos_wt[r0 + row + 8];
#pragma unroll
        for (int nt = 0; nt < 2; nt++) {
            int col = ncol + nt * 8 + 2 * (lane & 3);
            float* cc = c[mt][nt];
            *(float2*)(g_y + (size_t)(r0 + row) * D_DIM + c0 + col)
                = make_float2(cc[0] * wa, cc[1] * wa);
            *(float2*)(g_y + (size_t)(r0 + row + 8) * D_DIM + c0 + col)
                = make_float2(cc[2] * wb, cc[3] * wb);
        }
    }
}

// ---------------- combine ----------------------------------------------------
__global__ void combine_kernel(float* __restrict__ out, int T) {
    int idx = blockIdx.x * blockDim.x + threadIdx.x;
    int total = T * (D_DIM / 4);
    if (idx >= total) return;
    int t = idx / (D_DIM / 4);
    int d4 = idx - t * (D_DIM / 4);
    int p0 = g_slot_pos[2 * t];
    int p1 = g_slot_pos[2 * t + 1];
    const float4* y0 = (const float4*)(g_y + (size_t)p0 * D_DIM) + d4;
    const float4* y1 = (const float4*)(g_y + (size_t)p1 * D_DIM) + d4;
    float4 a = *y0, b = *y1;
    float4 r;
    r.x = a.x + b.x; r.y = a.y + b.y; r.z = a.z + b.z; r.w = a.w + b.w;
    ((float4*)out)[idx] = r;
}

// ---------------- launch -----------------------------------------------------
extern "C" void kernel_launch(void* const* d_in, const int* in_sizes, int n_in,
                              void* d_out, int out_size) {
    const float* x  = (const float*)d_in[0];
    const float* gw = (const float*)d_in[1];
    const float* w1 = (const float*)d_in[2];
    const float* w2 = (const float*)d_in[3];
    const float* w3 = (const float*)d_in[4];
    float* out = (float*)d_out;

    int T = in_sizes[0] / D_DIM;
    if (T > T_MAX) T = T_MAX;

    cudaFuncSetAttribute(gemm1_kernel, cudaFuncAttributeMaxDynamicSharedMemorySize, SMEM1);
    cudaFuncSetAttribute(gemm2_kernel, cudaFuncAttributeMaxDynamicSharedMemorySize, SMEM2);

    init_kernel<<<(NPOS + 255) / 256, 256>>>();
    gate_kernel<<<(T * 32 + 255) / 256, 256>>>(x, gw, T);
    offsets_kernel<<<1, 32>>>();
    scatter_kernel<<<(T * TOPK + 255) / 256, 256>>>(T);

    dim3 grid1(I_DIM / 64, NROWTILE);
    gemm1_kernel<<<grid1, 512, SMEM1>>>(x, w1, w3);

    dim3 grid2(D_DIM / 64, NROWTILE);
    gemm2_kernel<<<grid2, 512, SMEM2>>>(w2);

    combine_kernel<<<(T * (D_DIM / 4) + 255) / 256, 256>>>(out, T);
}